// round 1
// baseline (speedup 1.0000x reference)
#include <cuda_runtime.h>
#include <cstdint>

typedef unsigned long long ull;

#define Bb 2048
#define Tt 1000
#define Ii 40
#define Hh 16
#define TS 20
#define NCH (Tt/TS)
#define PADF 8
#define BSTR (TS*Ii + PADF)     /* 808 floats per batch-sub slot */
#define BUFF (2*BSTR)           /* 1616 floats per buffer (2 batch elems) */

// -------- prep-kernel outputs (device globals: no allocation allowed) --------
__device__ float4 g_wpack[Hh*20];   // {w_br0[2k], w_br0[2k+1], w_br1[2k], w_br1[2k+1]}
__device__ float  g_alpha[Hh], g_omalpha[Hh];
__device__ float2 g_beta[Hh], g_ombeta[Hh];
__device__ float2 g_w2[Hh];         // (W2[0][h], W2[1][h])
__device__ float2 g_b2c;

// -------- packed f32x2 helpers --------
__device__ __forceinline__ ull pk2(float a, float b){ ull r; asm("mov.b64 %0,{%1,%2};":"=l"(r):"f"(a),"f"(b)); return r; }
__device__ __forceinline__ void upk2(ull v, float&a, float&b){ asm("mov.b64 {%0,%1},%2;":"=f"(a),"=f"(b):"l"(v)); }
__device__ __forceinline__ ull fma2(ull a, ull b, ull c){ ull d; asm("fma.rn.f32x2 %0,%1,%2,%3;":"=l"(d):"l"(a),"l"(b),"l"(c)); return d; }
__device__ __forceinline__ ull mul2(ull a, ull b){ ull d; asm("mul.rn.f32x2 %0,%1,%2;":"=l"(d):"l"(a),"l"(b)); return d; }
__device__ __forceinline__ ull lds64v(uint32_t a){ ull r; asm volatile("ld.shared.b64 %0,[%1];":"=l"(r):"r"(a)); return r; }
__device__ __forceinline__ void cpa16(uint32_t d, const void* s){ asm volatile("cp.async.cg.shared.global [%0],[%1],16;"::"r"(d),"l"(s)); }
__device__ __forceinline__ void cp_commit(){ asm volatile("cp.async.commit_group;"); }

// ---------------- prep: pack weights / decays, init scalar outputs ----------------
__global__ void prep_kernel(const float* __restrict__ W1, const float* __restrict__ tau_m,
                            const float* __restrict__ tau_n, const float* __restrict__ mask,
                            const float* __restrict__ W2, const float* __restrict__ b2,
                            float* __restrict__ out, long long corrIdx, long long totIdx){
  int h = threadIdx.x;
  if (h < Hh){
    float a = 1.0f/(1.0f + expf(-tau_m[h]));
    g_alpha[h] = a; g_omalpha[h] = 1.0f - a;
    float be0 = 1.0f/(1.0f+expf(-tau_n[h*2+0]));
    float be1 = 1.0f/(1.0f+expf(-tau_n[h*2+1]));
    g_beta[h]   = make_float2(be0, be1);
    g_ombeta[h] = make_float2(1.0f-be0, 1.0f-be1);
    g_w2[h] = make_float2(W2[h], W2[Hh+h]);
    int r0 = (2*h)*Ii, r1 = (2*h+1)*Ii;
    for (int k=0;k<20;k++){
      float4 w;
      w.x = W1[r0+2*k]  *mask[r0+2*k];
      w.y = W1[r0+2*k+1]*mask[r0+2*k+1];
      w.z = W1[r1+2*k]  *mask[r1+2*k];
      w.w = W1[r1+2*k+1]*mask[r1+2*k+1];
      g_wpack[h*20+k] = w;
    }
  }
  if (h==0){
    g_b2c = make_float2(b2[0], b2[1]);
    out[0] = 0.0f;
    out[corrIdx] = 0.0f;
    int cnt = 0;
    for (int t=0;t<Tt;t++) cnt += ((t>10) && (((t-10)%15)>5)) ? 1 : 0;
    out[totIdx] = (float)cnt * (float)Bb;     // flags.sum() * B
  }
}

// ---------------- main: sequential SNN recurrence, warp = 2 batch x 16 neurons ----------------
__global__ void __launch_bounds__(32) snn_kernel(const float* __restrict__ x, float* __restrict__ out){
  __shared__ float sx[2*BUFF];
  const int lane = threadIdx.x;
  const int bsub = lane >> 4;
  const int h    = lane & 15;
  const int b0   = blockIdx.x * 2;

  ull wa[20], wb[20];
  #pragma unroll
  for (int k=0;k<20;k++){ float4 w = g_wpack[h*20+k]; wa[k]=pk2(w.x,w.y); wb[k]=pk2(w.z,w.w); }
  const float alpha = g_alpha[h], oma = g_omalpha[h];
  const float2 bt  = g_beta[h];
  const float2 omb = g_ombeta[h];
  const float2 w2  = g_w2[h];
  const float2 b2v = g_b2c;

  float d0=0.f, d1=0.f, mem=0.f, spk=0.f;
  uint32_t sbase = (uint32_t)__cvta_generic_to_shared(sx);

  const int b = b0 + bsub;
  float* outz = out + 1 + (size_t)b * Tt * 2;

  const float4* xg0 = (const float4*)x + (size_t)b0     * Tt * 10;   // 40 f32 = 10 float4 per step
  const float4* xg1 = (const float4*)x + (size_t)(b0+1) * Tt * 10;

  // stage chunk 0
  {
    for (int j=lane;j<400;j+=32){
      int bs = (j>=200); int pos = j - bs*200;
      cpa16(sbase + (uint32_t)(bs*202+pos)*16u, (bs? xg1:xg0) + pos);
    }
    cp_commit();
  }

  int buf = 0;
  for (int c=0;c<NCH;c++){
    if (c+1 < NCH){
      uint32_t sb = sbase + (uint32_t)((buf^1)*BUFF)*4u;
      const float4* p0 = xg0 + (size_t)(c+1)*TS*10;
      const float4* p1 = xg1 + (size_t)(c+1)*TS*10;
      for (int j=lane;j<400;j+=32){
        int bs = (j>=200); int pos = j - bs*200;
        cpa16(sb + (uint32_t)(bs*202+pos)*16u, (bs? p1:p0) + pos);
      }
      cp_commit();
      asm volatile("cp.async.wait_group 1;" ::: "memory");
    } else {
      asm volatile("cp.async.wait_group 0;" ::: "memory");
    }
    __syncwarp();

    uint32_t xaddr = sbase + (uint32_t)(buf*BUFF + bsub*BSTR)*4u;
    #pragma unroll 4
    for (int tt=0; tt<TS; tt++){
      // dense masked dot: 20 LDS.64 x-pairs, 40 FFMA2 (4 accumulator chains for ILP)
      ull xp0 = lds64v(xaddr);
      ull xp1 = lds64v(xaddr + 8u);
      ull a0 = mul2(wa[0], xp0), a1 = mul2(wb[0], xp0);
      ull q0 = mul2(wa[1], xp1), q1 = mul2(wb[1], xp1);
      #pragma unroll
      for (int k=2;k<20;k+=2){
        ull xa = lds64v(xaddr + 8u*k);
        ull xb = lds64v(xaddr + 8u*k + 8u);
        a0 = fma2(wa[k],   xa, a0);
        a1 = fma2(wb[k],   xa, a1);
        q0 = fma2(wa[k+1], xb, q0);
        q1 = fma2(wb[k+1], xb, q1);
      }
      float f0,f1,f2,f3;
      upk2(a0,f0,f1); upk2(q0,f2,f3);
      float c0 = (f0+f1)+(f2+f3);
      upk2(a1,f0,f1); upk2(q1,f2,f3);
      float c1 = (f0+f1)+(f2+f3);

      // dendritic + membrane recurrence
      d0 = fmaf(bt.x, d0, omb.x*c0);
      d1 = fmaf(bt.y, d1, omb.y*c1);
      float l = d0 + d1;
      mem = fmaf(alpha, mem - spk, oma*l);
      spk = (mem > 1.0f) ? 1.0f : 0.0f;

      // logits: butterfly reduce over the 16 neuron lanes of this batch element
      float e0 = spk*w2.x, e1 = spk*w2.y;
      #pragma unroll
      for (int off=1; off<16; off<<=1){
        e0 += __shfl_xor_sync(0xffffffffu, e0, off);
        e1 += __shfl_xor_sync(0xffffffffu, e1, off);
      }
      if (h==0){
        outz[0] = e0 + b2v.x;
        outz[1] = e1 + b2v.y;
      }
      outz += 2;
      xaddr += Ii*4;
    }
    __syncwarp();
    buf ^= 1;
  }
}

// ---------------- loss / accuracy: parallel over (b,t), reads logits back ----------------
__global__ void loss_kernel(const float* __restrict__ out_r, const int* __restrict__ target,
                            float* __restrict__ out, long long corrIdx){
  int idx = blockIdx.x * blockDim.x + threadIdx.x;
  float lossv = 0.f, corr = 0.f;
  if (idx < Bb*Tt){
    int t = idx % Tt;
    if ((t>10) && (((t-10)%15)>5)){
      float z0 = out_r[1 + 2*(size_t)idx];
      float z1 = out_r[2 + 2*(size_t)idx];
      int tgt = target[idx];
      float mz = fmaxf(z0,z1);
      float q0 = __expf(z0-mz), q1 = __expf(z1-mz);
      float r  = 1.0f/(q0+q1);
      float p0 = q0*r, p1 = q1*r;                       // softmax(logits)
      float M  = fmaxf(p0,p1);
      float lse = M + __logf(__expf(p0-M)+__expf(p1-M)); // log-sum-exp of p (double softmax)
      lossv = (lse - ((tgt==0)?p0:p1)) * (1.0f/(float)Bb);
      corr  = ((((p1>p0)?1:0)==tgt)) ? 1.0f : 0.0f;
    }
  }
  #pragma unroll
  for (int off=16; off; off>>=1){
    lossv += __shfl_xor_sync(0xffffffffu, lossv, off);
    corr  += __shfl_xor_sync(0xffffffffu, corr,  off);
  }
  __shared__ float sl[32], sc[32];
  int w = threadIdx.x>>5, ln = threadIdx.x&31;
  if (ln==0){ sl[w]=lossv; sc[w]=corr; }
  __syncthreads();
  if (w==0){
    int nw = blockDim.x>>5;
    lossv = (ln<nw)? sl[ln]:0.f;
    corr  = (ln<nw)? sc[ln]:0.f;
    #pragma unroll
    for (int off=4; off; off>>=1){
      lossv += __shfl_xor_sync(0xffffffffu,lossv,off);
      corr  += __shfl_xor_sync(0xffffffffu,corr, off);
    }
    if (ln==0){ atomicAdd(out, lossv); atomicAdd(out+corrIdx, corr); }
  }
}

extern "C" void kernel_launch(void* const* d_in, const int* in_sizes, int n_in,
                              void* d_out, int out_size){
  const float* x      = (const float*)d_in[0];
  const int*   target = (const int*)  d_in[1];
  const float* W1     = (const float*)d_in[2];
  const float* tau_m  = (const float*)d_in[3];
  const float* tau_n  = (const float*)d_in[4];
  const float* mask   = (const float*)d_in[5];
  const float* W2     = (const float*)d_in[6];
  const float* b2     = (const float*)d_in[7];
  float* out = (float*)d_out;
  long long corrIdx = (long long)out_size - 2;   // layout: [loss, logits(B*T*2), correct, total]
  long long totIdx  = (long long)out_size - 1;

  prep_kernel<<<1, 32>>>(W1, tau_m, tau_n, mask, W2, b2, out, corrIdx, totIdx);
  snn_kernel<<<Bb/2, 32>>>(x, out);
  loss_kernel<<<(Bb*Tt + 255)/256, 256>>>(out, target, out, corrIdx);
}

// round 2
// speedup vs baseline: 1.0813x; 1.0813x over previous
#include <cuda_runtime.h>
#include <cstdint>

typedef unsigned long long ull;

#define Bb 2048
#define Tt 1000
#define Ii 40
#define Hh 16
#define TS 20
#define NCH (Tt/TS)
#define PADF 8
#define BSTR (TS*Ii + PADF)     /* 808 floats per batch-sub slot (16B aligned) */
#define BUFF (2*BSTR)           /* per-buffer floats (2 batch elems) */

// -------- device-global scratch (no allocation allowed) --------
__device__ float4 g_wpack[Hh*20];     // {w_br0[2k], w_br0[2k+1], w_br1[2k], w_br1[2k+1]}
__device__ float  g_alpha[Hh], g_omalpha[Hh];
__device__ float2 g_beta[Hh], g_ombeta[Hh];
__device__ float2 g_w2[Hh];           // (W2[0][h], W2[1][h])
__device__ float2 g_b2c;
__device__ uint32_t g_masks[(Bb/2)*Tt];   // per-warp 32-bit spike masks (4 MB)

// -------- packed f32x2 helpers --------
__device__ __forceinline__ ull pk2(float a, float b){ ull r; asm("mov.b64 %0,{%1,%2};":"=l"(r):"f"(a),"f"(b)); return r; }
__device__ __forceinline__ void upk2(ull v, float&a, float&b){ asm("mov.b64 {%0,%1},%2;":"=f"(a),"=f"(b):"l"(v)); }
__device__ __forceinline__ ull fma2(ull a, ull b, ull c){ ull d; asm("fma.rn.f32x2 %0,%1,%2,%3;":"=l"(d):"l"(a),"l"(b),"l"(c)); return d; }
__device__ __forceinline__ ull mul2(ull a, ull b){ ull d; asm("mul.rn.f32x2 %0,%1,%2;":"=l"(d):"l"(a),"l"(b)); return d; }
__device__ __forceinline__ ull add2(ull a, ull b){ ull d; asm("add.rn.f32x2 %0,%1,%2;":"=l"(d):"l"(a),"l"(b)); return d; }
// NOTE: not volatile -> compiler may software-pipeline across timesteps
__device__ __forceinline__ void lds128(uint32_t a, ull&u, ull&v){ asm("ld.shared.v2.b64 {%0,%1},[%2];":"=l"(u),"=l"(v):"r"(a)); }
__device__ __forceinline__ void cpa16(uint32_t d, const void* s){ asm volatile("cp.async.cg.shared.global [%0],[%1],16;"::"r"(d),"l"(s)); }
__device__ __forceinline__ void cp_commit(){ asm volatile("cp.async.commit_group;"); }
__device__ __forceinline__ void stg128_lane0(int lane, uint32_t* p, uint32_t a, uint32_t b, uint32_t c, uint32_t d){
  asm volatile("{ .reg .pred q; setp.eq.s32 q,%0,0; @q st.global.v4.b32 [%1],{%2,%3,%4,%5}; }"
               :: "r"(lane), "l"(p), "r"(a), "r"(b), "r"(c), "r"(d) : "memory");
}

// ---------------- prep: pack weights / decays, init scalar outputs ----------------
__global__ void prep_kernel(const float* __restrict__ W1, const float* __restrict__ tau_m,
                            const float* __restrict__ tau_n, const float* __restrict__ mask,
                            const float* __restrict__ W2, const float* __restrict__ b2,
                            float* __restrict__ out, long long corrIdx, long long totIdx){
  int h = threadIdx.x;
  if (h < Hh){
    float a = 1.0f/(1.0f + expf(-tau_m[h]));
    g_alpha[h] = a; g_omalpha[h] = 1.0f - a;
    float be0 = 1.0f/(1.0f+expf(-tau_n[h*2+0]));
    float be1 = 1.0f/(1.0f+expf(-tau_n[h*2+1]));
    g_beta[h]   = make_float2(be0, be1);
    g_ombeta[h] = make_float2(1.0f-be0, 1.0f-be1);
    g_w2[h] = make_float2(W2[h], W2[Hh+h]);
    int r0 = (2*h)*Ii, r1 = (2*h+1)*Ii;
    for (int k=0;k<20;k++){
      float4 w;
      w.x = W1[r0+2*k]  *mask[r0+2*k];
      w.y = W1[r0+2*k+1]*mask[r0+2*k+1];
      w.z = W1[r1+2*k]  *mask[r1+2*k];
      w.w = W1[r1+2*k+1]*mask[r1+2*k+1];
      g_wpack[h*20+k] = w;
    }
  }
  if (h==0){
    g_b2c = make_float2(b2[0], b2[1]);
    out[0] = 0.0f;
    out[corrIdx] = 0.0f;
    int cnt = 0;
    for (int t=0;t<Tt;t++) cnt += ((t>10) && (((t-10)%15)>5)) ? 1 : 0;
    out[totIdx] = (float)cnt * (float)Bb;     // flags.sum() * B
  }
}

// ---------------- main: sequential SNN recurrence, warp = 2 batch x 16 neurons ----------------
// Per step: 10x LDS.128 (broadcast) + 40 FFMA2 + recurrence + 1 ballot.
// Spike masks (32-bit: low 16 = batch b0, high 16 = b0+1) stored 4-at-a-time via
// predicated STG.128 (no divergent branch in the serial loop).
__global__ void __launch_bounds__(32) snn_kernel(const float* __restrict__ x){
  __shared__ __align__(16) float sx[2*BUFF];
  const int lane = threadIdx.x;
  const int bsub = lane >> 4;
  const int h    = lane & 15;
  const int b0   = blockIdx.x * 2;

  ull wa[20], wb[20];
  #pragma unroll
  for (int k=0;k<20;k++){ float4 w = g_wpack[h*20+k]; wa[k]=pk2(w.x,w.y); wb[k]=pk2(w.z,w.w); }
  const float alpha = g_alpha[h], oma = g_omalpha[h];
  const float2 bt  = g_beta[h];
  const float2 omb = g_ombeta[h];

  float d0=0.f, d1=0.f, mem=0.f, spk=0.f;
  uint32_t sbase = (uint32_t)__cvta_generic_to_shared(sx);

  uint32_t* mrow = g_masks + (size_t)blockIdx.x * Tt;

  const float4* xg0 = (const float4*)x + (size_t)b0     * Tt * 10;   // 40 f32 = 10 float4/step
  const float4* xg1 = (const float4*)x + (size_t)(b0+1) * Tt * 10;

  // stage chunk 0
  for (int j=lane;j<400;j+=32){
    int bs = (j>=200); int pos = j - bs*200;
    cpa16(sbase + (uint32_t)(bs*202+pos)*16u, (bs? xg1:xg0) + pos);
  }
  cp_commit();

  int buf = 0;
  for (int c=0;c<NCH;c++){
    if (c+1 < NCH){
      uint32_t sb = sbase + (uint32_t)((buf^1)*BUFF)*4u;
      const float4* p0 = xg0 + (size_t)(c+1)*TS*10;
      const float4* p1 = xg1 + (size_t)(c+1)*TS*10;
      for (int j=lane;j<400;j+=32){
        int bs = (j>=200); int pos = j - bs*200;
        cpa16(sb + (uint32_t)(bs*202+pos)*16u, (bs? p1:p0) + pos);
      }
      cp_commit();
      asm volatile("cp.async.wait_group 1;" ::: "memory");
    } else {
      asm volatile("cp.async.wait_group 0;" ::: "memory");
    }
    __syncwarp();

    uint32_t xaddr = sbase + (uint32_t)(buf*BUFF + bsub*BSTR)*4u;

    #pragma unroll
    for (int g=0; g<TS/4; g++){
      uint32_t mb0, mb1, mb2, mb3;
      #pragma unroll
      for (int u=0; u<4; u++){
        // 40-float dense masked dot, both branches: 10 LDS.128 -> 20 ull x-pairs
        ull p[20];
        #pragma unroll
        for (int j=0;j<10;j++) lds128(xaddr + 16u*j, p[2*j], p[2*j+1]);

        ull a0 = mul2(wa[0], p[0]), a1 = mul2(wa[1], p[1]);
        ull b0c = mul2(wb[0], p[0]), b1c = mul2(wb[1], p[1]);
        #pragma unroll
        for (int k=2;k<20;k+=2){
          a0  = fma2(wa[k],   p[k],   a0);
          a1  = fma2(wa[k+1], p[k+1], a1);
          b0c = fma2(wb[k],   p[k],   b0c);
          b1c = fma2(wb[k+1], p[k+1], b1c);
        }
        float f0,f1;
        ull s0 = add2(a0,a1);  upk2(s0,f0,f1); float c0 = f0+f1;
        ull s1 = add2(b0c,b1c); upk2(s1,f0,f1); float c1 = f0+f1;

        // dendritic + membrane recurrence (the only true serial chain)
        d0 = fmaf(bt.x, d0, omb.x*c0);
        d1 = fmaf(bt.y, d1, omb.y*c1);
        float l = d0 + d1;
        mem = fmaf(alpha, mem - spk, oma*l);
        bool sp = mem > 1.0f;
        spk = sp ? 1.0f : 0.0f;
        uint32_t m = __ballot_sync(0xffffffffu, sp);
        if (u==0) mb0 = m; else if (u==1) mb1 = m; else if (u==2) mb2 = m; else mb3 = m;

        xaddr += Ii*4;
      }
      stg128_lane0(lane, mrow, mb0, mb1, mb2, mb3);
      mrow += 4;
    }
    __syncwarp();
    buf ^= 1;
  }
}

// ---------------- logits + loss + accuracy from spike masks (fully parallel) ----------------
__global__ void loss_kernel(const int* __restrict__ target, float* __restrict__ out,
                            long long corrIdx){
  // LUT: logits contribution of each 8-neuron spike sub-mask
  __shared__ float2 lut0[256], lut1[256];
  for (int m = threadIdx.x; m < 256; m += blockDim.x){
    float2 a = make_float2(0.f,0.f), b = make_float2(0.f,0.f);
    #pragma unroll
    for (int j=0;j<8;j++){
      if ((m>>j)&1){
        float2 w = g_w2[j];   a.x += w.x; a.y += w.y;
        float2 v = g_w2[8+j]; b.x += v.x; b.y += v.y;
      }
    }
    lut0[m]=a; lut1[m]=b;
  }
  __syncthreads();

  int idx = blockIdx.x * blockDim.x + threadIdx.x;
  float lossv = 0.f, corr = 0.f;
  if (idx < Bb*Tt){
    int b = idx / Tt;
    int t = idx - b*Tt;
    uint32_t w32 = g_masks[(size_t)(b>>1)*Tt + t];
    uint32_t m16 = (w32 >> ((b&1)<<4)) & 0xFFFFu;
    float2 lo = lut0[m16 & 0xFF];
    float2 hi = lut1[(m16 >> 8) & 0xFF];
    float2 b2v = g_b2c;
    float z0 = lo.x + hi.x + b2v.x;
    float z1 = lo.y + hi.y + b2v.y;
    out[1 + 2*(size_t)idx]     = z0;
    out[1 + 2*(size_t)idx + 1] = z1;
    if ((t>10) && (((t-10)%15)>5)){
      int tgt = target[idx];
      float mz = fmaxf(z0,z1);
      float q0 = __expf(z0-mz), q1 = __expf(z1-mz);
      float r  = 1.0f/(q0+q1);
      float p0 = q0*r, p1 = q1*r;                        // softmax(logits)
      float M  = fmaxf(p0,p1);
      float lse = M + __logf(__expf(p0-M)+__expf(p1-M)); // log-sum-exp of p (double softmax)
      lossv = (lse - ((tgt==0)?p0:p1)) * (1.0f/(float)Bb);
      corr  = ((((p1>p0)?1:0)==tgt)) ? 1.0f : 0.0f;
    }
  }
  #pragma unroll
  for (int off=16; off; off>>=1){
    lossv += __shfl_xor_sync(0xffffffffu, lossv, off);
    corr  += __shfl_xor_sync(0xffffffffu, corr,  off);
  }
  __shared__ float sl[32], sc[32];
  int w = threadIdx.x>>5, ln = threadIdx.x&31;
  if (ln==0){ sl[w]=lossv; sc[w]=corr; }
  __syncthreads();
  if (w==0){
    int nw = blockDim.x>>5;
    lossv = (ln<nw)? sl[ln]:0.f;
    corr  = (ln<nw)? sc[ln]:0.f;
    #pragma unroll
    for (int off=4; off; off>>=1){
      lossv += __shfl_xor_sync(0xffffffffu,lossv,off);
      corr  += __shfl_xor_sync(0xffffffffu,corr, off);
    }
    if (ln==0){ atomicAdd(out, lossv); atomicAdd(out+corrIdx, corr); }
  }
}

extern "C" void kernel_launch(void* const* d_in, const int* in_sizes, int n_in,
                              void* d_out, int out_size){
  const float* x      = (const float*)d_in[0];
  const int*   target = (const int*)  d_in[1];
  const float* W1     = (const float*)d_in[2];
  const float* tau_m  = (const float*)d_in[3];
  const float* tau_n  = (const float*)d_in[4];
  const float* mask   = (const float*)d_in[5];
  const float* W2     = (const float*)d_in[6];
  const float* b2     = (const float*)d_in[7];
  float* out = (float*)d_out;
  long long corrIdx = (long long)out_size - 2;   // layout: [loss, logits(B*T*2), correct, total]
  long long totIdx  = (long long)out_size - 1;

  prep_kernel<<<1, 32>>>(W1, tau_m, tau_n, mask, W2, b2, out, corrIdx, totIdx);
  snn_kernel<<<Bb/2, 32>>>(x);
  loss_kernel<<<(Bb*Tt + 255)/256, 256>>>(target, out, corrIdx);
}

// round 3
// speedup vs baseline: 1.1772x; 1.0887x over previous
#include <cuda_runtime.h>
#include <cstdint>

typedef unsigned long long ull;

#define Bb 2048
#define Tt 1000
#define Ii 40
#define Hh 16
#define TS 20
#define NCH (Tt/TS)
#define PADF 8
#define BSTR (TS*Ii + PADF)     /* 808 floats per batch-sub slot (16B aligned) */
#define BUFF (2*BSTR)           /* per-buffer floats (2 batch elems) */

// -------- device-global scratch (no allocation allowed) --------
__device__ float4 g_wpack[Hh*20];     // pre-scaled: branch0 pair *(oma*omb0), branch1 pair *(oma*omb1)
__device__ float  g_alpha[Hh];
__device__ float2 g_beta[Hh];
__device__ float2 g_w2[Hh];           // (W2[0][h], W2[1][h])
__device__ float2 g_b2c;
__device__ uint32_t g_masks[(Bb/2)*Tt];   // per-warp 32-bit spike masks (4 MB)

// -------- packed f32x2 helpers --------
__device__ __forceinline__ ull pk2(float a, float b){ ull r; asm("mov.b64 %0,{%1,%2};":"=l"(r):"f"(a),"f"(b)); return r; }
__device__ __forceinline__ void upk2(ull v, float&a, float&b){ asm("mov.b64 {%0,%1},%2;":"=f"(a),"=f"(b):"l"(v)); }
__device__ __forceinline__ ull fma2(ull a, ull b, ull c){ ull d; asm("fma.rn.f32x2 %0,%1,%2,%3;":"=l"(d):"l"(a),"l"(b),"l"(c)); return d; }
__device__ __forceinline__ ull mul2(ull a, ull b){ ull d; asm("mul.rn.f32x2 %0,%1,%2;":"=l"(d):"l"(a),"l"(b)); return d; }
__device__ __forceinline__ ull add2(ull a, ull b){ ull d; asm("add.rn.f32x2 %0,%1,%2;":"=l"(d):"l"(a),"l"(b)); return d; }
// non-volatile: allow ptxas to schedule loads across steps
__device__ __forceinline__ void lds128(uint32_t a, ull&u, ull&v){ asm("ld.shared.v2.b64 {%0,%1},[%2];":"=l"(u),"=l"(v):"r"(a)); }
__device__ __forceinline__ void cpa16(uint32_t d, const void* s){ asm volatile("cp.async.cg.shared.global [%0],[%1],16;"::"r"(d),"l"(s)); }
__device__ __forceinline__ void cp_commit(){ asm volatile("cp.async.commit_group;"); }
__device__ __forceinline__ void stg32_lane0(int lane, uint32_t* p, uint32_t v){
  asm volatile("{ .reg .pred q; setp.eq.s32 q,%0,0; @q st.global.b32 [%1],%2; }"
               :: "r"(lane), "l"(p), "r"(v) : "memory");
}

// ---------------- prep: pack + pre-scale weights, init scalar outputs ----------------
__global__ void prep_kernel(const float* __restrict__ W1, const float* __restrict__ tau_m,
                            const float* __restrict__ tau_n, const float* __restrict__ mask,
                            const float* __restrict__ W2, const float* __restrict__ b2,
                            float* __restrict__ out, long long corrIdx, long long totIdx){
  int h = threadIdx.x;
  if (h < Hh){
    float a = 1.0f/(1.0f + expf(-tau_m[h]));
    g_alpha[h] = a;
    float oma = 1.0f - a;
    float be0 = 1.0f/(1.0f+expf(-tau_n[h*2+0]));
    float be1 = 1.0f/(1.0f+expf(-tau_n[h*2+1]));
    g_beta[h] = make_float2(be0, be1);
    float s0 = oma*(1.0f-be0);      // fold (1-alpha)*(1-beta0) into branch0 weights
    float s1 = oma*(1.0f-be1);
    g_w2[h] = make_float2(W2[h], W2[Hh+h]);
    int r0 = (2*h)*Ii, r1 = (2*h+1)*Ii;
    for (int k=0;k<20;k++){
      float4 w;
      w.x = W1[r0+2*k]  *mask[r0+2*k]  *s0;
      w.y = W1[r0+2*k+1]*mask[r0+2*k+1]*s0;
      w.z = W1[r1+2*k]  *mask[r1+2*k]  *s1;
      w.w = W1[r1+2*k+1]*mask[r1+2*k+1]*s1;
      g_wpack[h*20+k] = w;
    }
  }
  if (h==0){
    g_b2c = make_float2(b2[0], b2[1]);
    out[0] = 0.0f;
    out[corrIdx] = 0.0f;
    int cnt = 0;
    for (int t=0;t<Tt;t++) cnt += ((t>10) && (((t-10)%15)>5)) ? 1 : 0;
    out[totIdx] = (float)cnt * (float)Bb;     // flags.sum() * B
  }
}

// ---------------- main: sequential SNN recurrence, warp = 2 batch x 16 neurons ----------------
// Per step: 10x LDS.128 (broadcast) + 40 FFMA2 (4 chains) + trimmed recurrence + ballot + STG.32.
// Scales folded into weights: d' = beta*d' + dot_scaled; l' = d0'+d1';
// mem = alpha*mem + l' - (spk_prev ? alpha : 0); spike = mem > 1.
__global__ void __launch_bounds__(32) snn_kernel(const float* __restrict__ x){
  __shared__ __align__(16) float sx[2*BUFF];
  const int lane = threadIdx.x;
  const int bsub = lane >> 4;
  const int h    = lane & 15;
  const int b0   = blockIdx.x * 2;

  ull wa[20], wb[20];
  #pragma unroll
  for (int k=0;k<20;k++){ float4 w = g_wpack[h*20+k]; wa[k]=pk2(w.x,w.y); wb[k]=pk2(w.z,w.w); }
  const float alpha = g_alpha[h];
  const float2 bt  = g_beta[h];

  float d0=0.f, d1=0.f, mem=0.f;
  float asel = 0.f;                 // alpha if previous spike else 0 (computed off-path)
  uint32_t sbase = (uint32_t)__cvta_generic_to_shared(sx);

  uint32_t* mrow = g_masks + (size_t)blockIdx.x * Tt;

  const float4* xg0 = (const float4*)x + (size_t)b0     * Tt * 10;   // 40 f32 = 10 float4/step
  const float4* xg1 = (const float4*)x + (size_t)(b0+1) * Tt * 10;

  // stage chunk 0
  for (int j=lane;j<400;j+=32){
    int bs = (j>=200); int pos = j - bs*200;
    cpa16(sbase + (uint32_t)(bs*202+pos)*16u, (bs? xg1:xg0) + pos);
  }
  cp_commit();

  int buf = 0;
  for (int c=0;c<NCH;c++){
    if (c+1 < NCH){
      uint32_t sb = sbase + (uint32_t)((buf^1)*BUFF)*4u;
      const float4* p0 = xg0 + (size_t)(c+1)*TS*10;
      const float4* p1 = xg1 + (size_t)(c+1)*TS*10;
      for (int j=lane;j<400;j+=32){
        int bs = (j>=200); int pos = j - bs*200;
        cpa16(sb + (uint32_t)(bs*202+pos)*16u, (bs? p1:p0) + pos);
      }
      cp_commit();
      asm volatile("cp.async.wait_group 1;" ::: "memory");
    } else {
      asm volatile("cp.async.wait_group 0;" ::: "memory");
    }
    __syncwarp();

    uint32_t xaddr = sbase + (uint32_t)(buf*BUFF + bsub*BSTR)*4u;

    #pragma unroll 4
    for (int tt=0; tt<TS; tt++){
      // dense masked dot, both branches: 10 LDS.128 -> 20 ull x-pairs, consumed immediately
      ull p0a, p0b;
      lds128(xaddr, p0a, p0b);
      ull a0 = mul2(wa[0], p0a), a1 = mul2(wa[1], p0b);
      ull q0 = mul2(wb[0], p0a), q1 = mul2(wb[1], p0b);
      #pragma unroll
      for (int j=1;j<10;j++){
        ull xa, xb;
        lds128(xaddr + 16u*j, xa, xb);
        a0 = fma2(wa[2*j],   xa, a0);
        a1 = fma2(wa[2*j+1], xb, a1);
        q0 = fma2(wb[2*j],   xa, q0);
        q1 = fma2(wb[2*j+1], xb, q1);
      }
      float f0,f1;
      ull s0 = add2(a0,a1); upk2(s0,f0,f1); float c0 = f0+f1;   // already scaled by oma*omb0
      ull s1 = add2(q0,q1); upk2(s1,f0,f1); float c1 = f0+f1;

      // recurrence (folded scales): d' = beta*d' + c; mem = alpha*mem + l - asel_prev
      d0 = fmaf(bt.x, d0, c0);
      d1 = fmaf(bt.y, d1, c1);
      float l = d0 + d1;
      mem = fmaf(alpha, mem, l) - asel;
      bool sp = mem > 1.0f;
      asel = sp ? alpha : 0.0f;                      // for next step, off critical path
      uint32_t m = __ballot_sync(0xffffffffu, sp);
      stg32_lane0(lane, mrow + tt, m);

      xaddr += Ii*4;
    }
    mrow += TS;
    __syncwarp();
    buf ^= 1;
  }
}

// ---------------- logits + loss + accuracy from spike masks (fully parallel) ----------------
__global__ void loss_kernel(const int* __restrict__ target, float* __restrict__ out,
                            long long corrIdx){
  // LUT: logits contribution of each 8-neuron spike sub-mask
  __shared__ float2 lut0[256], lut1[256];
  for (int m = threadIdx.x; m < 256; m += blockDim.x){
    float2 a = make_float2(0.f,0.f), b = make_float2(0.f,0.f);
    #pragma unroll
    for (int j=0;j<8;j++){
      if ((m>>j)&1){
        float2 w = g_w2[j];   a.x += w.x; a.y += w.y;
        float2 v = g_w2[8+j]; b.x += v.x; b.y += v.y;
      }
    }
    lut0[m]=a; lut1[m]=b;
  }
  __syncthreads();

  int idx = blockIdx.x * blockDim.x + threadIdx.x;
  float lossv = 0.f, corr = 0.f;
  if (idx < Bb*Tt){
    int b = idx / Tt;
    int t = idx - b*Tt;
    uint32_t w32 = g_masks[(size_t)(b>>1)*Tt + t];
    uint32_t m16 = (w32 >> ((b&1)<<4)) & 0xFFFFu;
    float2 lo = lut0[m16 & 0xFF];
    float2 hi = lut1[(m16 >> 8) & 0xFF];
    float2 b2v = g_b2c;
    float z0 = lo.x + hi.x + b2v.x;
    float z1 = lo.y + hi.y + b2v.y;
    out[1 + 2*(size_t)idx]     = z0;
    out[1 + 2*(size_t)idx + 1] = z1;
    if ((t>10) && (((t-10)%15)>5)){
      int tgt = target[idx];
      float mz = fmaxf(z0,z1);
      float q0 = __expf(z0-mz), q1 = __expf(z1-mz);
      float r  = 1.0f/(q0+q1);
      float p0 = q0*r, p1 = q1*r;                        // softmax(logits)
      float M  = fmaxf(p0,p1);
      float lse = M + __logf(__expf(p0-M)+__expf(p1-M)); // log-sum-exp of p (double softmax)
      lossv = (lse - ((tgt==0)?p0:p1)) * (1.0f/(float)Bb);
      corr  = ((((p1>p0)?1:0)==tgt)) ? 1.0f : 0.0f;
    }
  }
  #pragma unroll
  for (int off=16; off; off>>=1){
    lossv += __shfl_xor_sync(0xffffffffu, lossv, off);
    corr  += __shfl_xor_sync(0xffffffffu, corr,  off);
  }
  __shared__ float sl[32], sc[32];
  int w = threadIdx.x>>5, ln = threadIdx.x&31;
  if (ln==0){ sl[w]=lossv; sc[w]=corr; }
  __syncthreads();
  if (w==0){
    int nw = blockDim.x>>5;
    lossv = (ln<nw)? sl[ln]:0.f;
    corr  = (ln<nw)? sc[ln]:0.f;
    #pragma unroll
    for (int off=4; off; off>>=1){
      lossv += __shfl_xor_sync(0xffffffffu,lossv,off);
      corr  += __shfl_xor_sync(0xffffffffu,corr, off);
    }
    if (ln==0){ atomicAdd(out, lossv); atomicAdd(out+corrIdx, corr); }
  }
}

extern "C" void kernel_launch(void* const* d_in, const int* in_sizes, int n_in,
                              void* d_out, int out_size){
  const float* x      = (const float*)d_in[0];
  const int*   target = (const int*)  d_in[1];
  const float* W1     = (const float*)d_in[2];
  const float* tau_m  = (const float*)d_in[3];
  const float* tau_n  = (const float*)d_in[4];
  const float* mask   = (const float*)d_in[5];
  const float* W2     = (const float*)d_in[6];
  const float* b2     = (const float*)d_in[7];
  float* out = (float*)d_out;
  long long corrIdx = (long long)out_size - 2;   // layout: [loss, logits(B*T*2), correct, total]
  long long totIdx  = (long long)out_size - 1;

  prep_kernel<<<1, 32>>>(W1, tau_m, tau_n, mask, W2, b2, out, corrIdx, totIdx);
  snn_kernel<<<Bb/2, 32>>>(x);
  loss_kernel<<<(Bb*Tt + 255)/256, 256>>>(target, out, corrIdx);
}